// round 15
// baseline (speedup 1.0000x reference)
#include <cuda_runtime.h>
#include <cuda_bf16.h>
#include <math.h>

#define NE 100000
#define D  64
#define NEDGE 1000000
#define NR 32
#define SCAN_B 1024
#define NB ((NE + SCAN_B - 1) / SCAN_B)   // 98
#define RBIN 32768                        // slots per relation bin (mult of 128)
#define PADE (NR * RBIN)                  // 1048576
#define NBLK_ATT (PADE / 128)             // 8192
#define NBLK_Q   ((NE + 127) / 128)       // 782

// ------------- device scratch ----------------------------------------------
__device__ __align__(256) unsigned g_aggH[NE * 32];     // bf16x2 agg rows (current)
__device__ __align__(256) unsigned g_aggH2[NE * 32];    // bf16x2 agg rows (next)
__device__ __align__(256) unsigned g_Qu[NE * 32];       // bf16x2 Q rows
__device__ __align__(256) float    g_att[NEDGE];
__device__ __align__(256) float    g_attc[NEDGE];       // exp(att) in CSR order
__device__ __align__(256) unsigned g_KRt[NR * D * 32];  // bf16x2, [r][n][k2]
__device__ __align__(256) unsigned g_QWt[D * 32];       // bf16x2, [n][k2]
__device__ __align__(256) int      g_deg[NE];
__device__ __align__(256) int      g_fill[NE];
__device__ __align__(256) int      g_rowptr[NE + 1];
__device__ __align__(256) int      g_csr[NEDGE];
__device__ __align__(256) unsigned g_csrt[NEDGE];       // tail | etype<<17 in CSR order
__device__ __align__(256) int      g_part[NB + 8];
__device__ __align__(256) int      g_rfill[NR];
__device__ __align__(256) int      g_eord[PADE];

// ---------------- helpers ----------------
__device__ __forceinline__ unsigned pack_bf2(float lo, float hi) {
    __nv_bfloat162 b = __float22bfloat162_rn(make_float2(lo, hi));  // .x = lo
    return *reinterpret_cast<unsigned*>(&b);
}
__device__ __forceinline__ float2 unpack_bf2(unsigned u) {
    __nv_bfloat162 b = *reinterpret_cast<__nv_bfloat162*>(&u);
    return __bfloat1622float2(b);
}

__device__ __forceinline__ void mma_bf16(float& c0, float& c1, float& c2, float& c3,
                                         unsigned a0, unsigned a1, unsigned a2, unsigned a3,
                                         unsigned b0, unsigned b1) {
    asm("mma.sync.aligned.m16n8k16.row.col.f32.bf16.bf16.f32 "
        "{%0,%1,%2,%3},{%4,%5,%6,%7},{%8,%9},{%0,%1,%2,%3};"
        : "+f"(c0), "+f"(c1), "+f"(c2), "+f"(c3)
        : "r"(a0), "r"(a1), "r"(a2), "r"(a3), "r"(b0), "r"(b1));
}

// cp.async 16B helper
__device__ __forceinline__ void cpa16(void* sptr, const void* gptr) {
    unsigned sa = (unsigned)__cvta_generic_to_shared(sptr);
    asm volatile("cp.async.cg.shared.global [%0], [%1], 16;" :: "r"(sa), "l"(gptr));
}
__device__ __forceinline__ void cpa_commit() {
    asm volatile("cp.async.commit_group;");
}
template <int N>
__device__ __forceinline__ void cpa_wait() {
    asm volatile("cp.async.wait_group %0;" :: "n"(N));
}

// Taylor-7 tanh: |s| small; clamp at +-1.
__device__ __forceinline__ float tanhp(float x) {
    x = fminf(1.0f, fmaxf(-1.0f, x));
    float u = x * x;
    float p = fmaf(u, -17.0f / 315.0f, 2.0f / 15.0f);
    p = fmaf(u, p, -1.0f / 3.0f);
    p = fmaf(u, p, 1.0f);
    return x * p;
}

#define XU_STRIDE 36   // u32; 144B rows: 16B aligned, conflict-free LDS patterns

// ---------------- prep: packed bf16 weights + ent->bf16 + init -------------
__global__ void k_prep(const float* __restrict__ ent, const float* __restrict__ edge_emb,
                       const float* __restrict__ kw, const float* __restrict__ qw) {
    int tid = blockIdx.x * blockDim.x + threadIdx.x;
    int st = gridDim.x * blockDim.x;
    for (int i = tid; i < NR * D * 32; i += st) {
        int r = i >> 11, rm = i & 2047;
        int n = rm >> 5, k2 = rm & 31;
        float rlo = edge_emb[r * 64 + 2 * k2], rhi = edge_emb[r * 64 + 2 * k2 + 1];
        float klo = kw[(2 * k2) * 64 + n],     khi = kw[(2 * k2 + 1) * 64 + n];
        g_KRt[i] = pack_bf2(rlo * klo, rhi * khi);
    }
    for (int i = tid; i < D * 32; i += st) {
        int n = i >> 5, k2 = i & 31;
        g_QWt[i] = pack_bf2(qw[(2 * k2) * 64 + n], qw[(2 * k2 + 1) * 64 + n]);
    }
    for (int i = tid; i < NE * 32; i += st) {
        int row = i >> 5, k2 = i & 31;
        g_aggH[i] = pack_bf2(ent[row * 64 + 2 * k2], ent[row * 64 + 2 * k2 + 1]);
    }
    for (int i = tid; i < NE; i += st) { g_deg[i] = 0; g_fill[i] = 0; }
    if (tid < NR) g_rfill[tid] = 0;
}

// ------ relation binning (block-aggregated atomics) + degree histogram -----
__global__ void k_ehist(const int* __restrict__ etype, const int* __restrict__ head) {
    __shared__ int hist[NR];
    __shared__ int rbase[NR];
    int tid = threadIdx.x;
    int e = blockIdx.x * blockDim.x + tid;
    if (tid < NR) hist[tid] = 0;
    __syncthreads();
    int r = 0, off = 0;
    bool valid = (e < NEDGE);
    if (valid) {
        r = etype[e];
        off = atomicAdd(&hist[r], 1);                 // smem atomic
        atomicAdd(&g_deg[head[e]], 1);                // 100K addrs: low contention
    }
    __syncthreads();
    if (tid < NR && hist[tid] > 0)
        rbase[tid] = atomicAdd(&g_rfill[tid], hist[tid]);  // 32 atomics/block
    __syncthreads();
    if (valid) g_eord[(r << 15) + rbase[r] + off] = e;
}

// ---------------- CSR build ----------------
__global__ void k_scan1() {
    __shared__ int sh[SCAN_B];
    int b = blockIdx.x, t = threadIdx.x;
    int i = b * SCAN_B + t;
    int v = (i < NE) ? g_deg[i] : 0;
    sh[t] = v;
    __syncthreads();
    #pragma unroll
    for (int off = 1; off < SCAN_B; off <<= 1) {
        int x = (t >= off) ? sh[t - off] : 0;
        __syncthreads();
        sh[t] += x;
        __syncthreads();
    }
    if (i < NE) g_rowptr[i] = sh[t] - v;
    if (t == SCAN_B - 1) g_part[b] = sh[t];
}

__global__ void k_scan2() {       // parallel exclusive scan over NB block sums
    __shared__ int sh[128];
    int t = threadIdx.x;
    int v = (t < NB) ? g_part[t] : 0;
    sh[t] = v;
    __syncthreads();
    #pragma unroll
    for (int off = 1; off < 128; off <<= 1) {
        int x = (t >= off) ? sh[t - off] : 0;
        __syncthreads();
        sh[t] += x;
        __syncthreads();
    }
    if (t < NB) g_part[t] = sh[t] - v;
}

__global__ void k_scan3() {
    int i = blockIdx.x * blockDim.x + threadIdx.x;
    if (i < NE) g_rowptr[i] += g_part[i >> 10];
    if (i == 0) g_rowptr[NE] = NEDGE;
}

__global__ void k_fill(const int* __restrict__ head, const int* __restrict__ tail,
                       const int* __restrict__ etype) {
    int e = blockIdx.x * blockDim.x + threadIdx.x;
    if (e < NEDGE) {
        int h = head[e];
        int p = g_rowptr[h] + atomicAdd(&g_fill[h], 1);
        g_csr[p] = e;
        g_csrt[p] = (unsigned)tail[e] | ((unsigned)etype[e] << 17);
    }
}

// ----- MMA core: per-warp M=16 (rows w*16..w*16+15), full N=64, K=64 -------
__device__ __forceinline__ void mma_core16(const unsigned* Xu, const unsigned* Bu,
                                           float acc[8][4], int w, int lane) {
    int grp = lane >> 2, c4 = lane & 3;
    #pragma unroll
    for (int s = 0; s < 4; s++) {
        int ar = w * 16 + grp;
        unsigned a0 = Xu[ar * XU_STRIDE + s * 8 + c4];
        unsigned a1 = Xu[(ar + 8) * XU_STRIDE + s * 8 + c4];
        unsigned a2 = Xu[ar * XU_STRIDE + s * 8 + c4 + 4];
        unsigned a3 = Xu[(ar + 8) * XU_STRIDE + s * 8 + c4 + 4];
        #pragma unroll
        for (int n = 0; n < 8; n++) {
            unsigned b0 = Bu[(n * 8 + grp) * XU_STRIDE + s * 8 + c4];
            unsigned b1 = Bu[(n * 8 + grp) * XU_STRIDE + s * 8 + c4 + 4];
            mma_bf16(acc[n][0], acc[n][1], acc[n][2], acc[n][3],
                     a0, a1, a2, a3, b0, b1);
        }
    }
}

// ---------------- Q = aggh @ q_w via bf16 mma (256 thr, 128 rows) ----------
__global__ void __launch_bounds__(256, 4) k_qmm(const unsigned* __restrict__ aggh) {
    __shared__ __align__(16) unsigned Xu[128 * XU_STRIDE];
    __shared__ __align__(16) unsigned Bu[64 * XU_STRIDE];
    int tid = threadIdx.x;
    int w = tid >> 5, lane = tid & 31;
    int i8 = lane & 7, r4 = lane >> 3;
    int base = blockIdx.x * 128;

    // X: 16 rows/warp, 4 rows per 16B cp.async
    #pragma unroll
    for (int rr = 0; rr < 4; rr++) {
        int row = w * 16 + rr * 4 + r4;
        int g = base + row;
        if (g < NE) {
            cpa16(&Xu[row * XU_STRIDE + i8 * 4], &aggh[g * 32 + i8 * 4]);
        } else {
            #pragma unroll
            for (int j = 0; j < 4; j++) Xu[row * XU_STRIDE + i8 * 4 + j] = 0u;
        }
    }
    // B: 512 16B chunks over 256 threads
    #pragma unroll
    for (int i = tid; i < 512; i += 256) {
        int n = i >> 3, c = i & 7;
        cpa16(&Bu[n * XU_STRIDE + c * 4], &g_QWt[i * 4]);
    }
    cpa_commit();
    cpa_wait<0>();
    __syncthreads();

    float acc[8][4];
    #pragma unroll
    for (int n = 0; n < 8; n++)
        #pragma unroll
        for (int q = 0; q < 4; q++) acc[n][q] = 0.0f;

    mma_core16(Xu, Bu, acc, w, lane);

    int grp = lane >> 2, c4 = lane & 3;
    int r0 = base + w * 16 + grp, r1 = r0 + 8;
    #pragma unroll
    for (int n = 0; n < 8; n++) {
        if (r0 < NE) g_Qu[r0 * 32 + n * 4 + c4] = pack_bf2(acc[n][0], acc[n][1]);
        if (r1 < NE) g_Qu[r1 * 32 + n * 4 + c4] = pack_bf2(acc[n][2], acc[n][3]);
    }
}

// ------- att[e] = <Q[head], tanh(aggh[tail] @ KR[r])> via bf16 mma ---------
__global__ void __launch_bounds__(256, 4) k_attmm(const unsigned* __restrict__ aggh,
                                                  const int* __restrict__ head,
                                                  const int* __restrict__ tail) {
    int base = blockIdx.x * 128;
    int rel = blockIdx.x >> 8;          // 256 blocks per static relation bin
    int cnt = g_rfill[rel] - ((blockIdx.x & 255) << 7);   // valid edges this block
    if (cnt <= 0) return;

    __shared__ __align__(16) unsigned Xu[128 * XU_STRIDE];
    __shared__ __align__(16) unsigned Bu[64 * XU_STRIDE];
    __shared__ __align__(16) unsigned Qs[128 * XU_STRIDE];
    __shared__ int es[128];
    __shared__ int tls[128];
    __shared__ int hds[128];
    int tid = threadIdx.x;
    int w = tid >> 5, lane = tid & 31;
    int i8 = lane & 7, r4 = lane >> 3;

    if (tid < 128) {
        int e = (tid < cnt) ? g_eord[base + tid] : -1;
        es[tid] = e;
        tls[tid] = (e >= 0) ? __ldg(&tail[e]) : 0;
        hds[tid] = (e >= 0) ? __ldg(&head[e]) : 0;
    }
    __syncthreads();

    // group A: X gather (4 rows per 16B instr) + B tile
    #pragma unroll
    for (int rr = 0; rr < 4; rr++) {
        int row = w * 16 + rr * 4 + r4;
        cpa16(&Xu[row * XU_STRIDE + i8 * 4], &aggh[tls[row] * 32 + i8 * 4]);
    }
    #pragma unroll
    for (int i = tid; i < 512; i += 256) {
        int n = i >> 3, c = i & 7;
        cpa16(&Bu[n * XU_STRIDE + c * 4], &g_KRt[rel * 2048 + i * 4]);
    }
    cpa_commit();
    // group B: Q rows prefetch (consumed after MMA, warp-local rows)
    #pragma unroll
    for (int rr = 0; rr < 4; rr++) {
        int row = w * 16 + rr * 4 + r4;
        cpa16(&Qs[row * XU_STRIDE + i8 * 4], &g_Qu[hds[row] * 32 + i8 * 4]);
    }
    cpa_commit();

    cpa_wait<1>();        // X + B landed; Q still in flight
    __syncthreads();

    float acc[8][4];
    #pragma unroll
    for (int n = 0; n < 8; n++)
        #pragma unroll
        for (int q = 0; q < 4; q++) acc[n][q] = 0.0f;

    mma_core16(Xu, Bu, acc, w, lane);

    cpa_wait<0>();        // Q rows landed (own warp's rows)
    __syncwarp();

    // epilogue: att = sum_j Q[head][j] * tanh(S[row][j]) from smem Qs
    int grp = lane >> 2, c4 = lane & 3;
    int rl0 = w * 16 + grp, rl1 = rl0 + 8;
    int e0 = es[rl0], e1 = es[rl1];
    float s0 = 0.0f, s1 = 0.0f;
    #pragma unroll
    for (int n = 0; n < 8; n++) {
        float2 q0 = unpack_bf2(Qs[rl0 * XU_STRIDE + n * 4 + c4]);
        float2 q1 = unpack_bf2(Qs[rl1 * XU_STRIDE + n * 4 + c4]);
        s0 = fmaf(q0.x, tanhp(acc[n][0]), fmaf(q0.y, tanhp(acc[n][1]), s0));
        s1 = fmaf(q1.x, tanhp(acc[n][2]), fmaf(q1.y, tanhp(acc[n][3]), s1));
    }
    s0 += __shfl_xor_sync(0xffffffffu, s0, 1);
    s0 += __shfl_xor_sync(0xffffffffu, s0, 2);
    s1 += __shfl_xor_sync(0xffffffffu, s1, 1);
    s1 += __shfl_xor_sync(0xffffffffu, s1, 2);
    if (c4 == 0) {
        if (e0 >= 0) g_att[e0] = s0;
        if (e1 >= 0) g_att[e1] = s1;
    }
}

// ------- softmax (no-max) + weighted mean (bf16 gather, ILP2) + l2norm -----
__global__ void __launch_bounds__(256) k_agg(const unsigned* __restrict__ aggh_in,
                                             unsigned* __restrict__ aggh_out,
                                             const float* __restrict__ ent,
                                             float* __restrict__ out,
                                             const float* __restrict__ edge_emb,
                                             int first) {
    __shared__ float2 rels[NR * 32];   // 8KB relation table, pair layout
    for (int i = threadIdx.x; i < NR * 32; i += 256)
        rels[i] = make_float2(edge_emb[2 * i], edge_emb[2 * i + 1]);
    __syncthreads();

    int w = (blockIdx.x * blockDim.x + threadIdx.x) >> 5;
    int l = threadIdx.x & 31;
    if (w >= NE) return;
    int s0 = g_rowptr[w], s1 = g_rowptr[w + 1];

    // pass 1: exp into CSR-ordered attc (random att read, sequential write)
    float den = 0.0f;
    for (int k = s0 + l; k < s1; k += 32) {
        float a = __expf(g_att[g_csr[k]]);
        g_attc[k] = a;
        den += a;
    }
    #pragma unroll
    for (int o = 16; o; o >>= 1) den += __shfl_xor_sync(0xffffffffu, den, o);
    float rinv = (den > 0.0f) ? (1.0f / den) : 0.0f;

    // pass 2: sequential metadata; 2 gathers in flight (ILP2)
    float acc0 = 0.0f, acc1 = 0.0f, acc0b = 0.0f, acc1b = 0.0f;
    int k = s0;
    for (; k + 1 < s1; k += 2) {
        unsigned pk0 = __ldg(&g_csrt[k]);
        unsigned pk1 = __ldg(&g_csrt[k + 1]);
        float w0 = __ldg(&g_attc[k]) * rinv;
        float w1 = __ldg(&g_attc[k + 1]) * rinv;
        int t0 = pk0 & 0x1FFFF, r0 = pk0 >> 17;
        int t1 = pk1 & 0x1FFFF, r1 = pk1 >> 17;
        float2 a0 = unpack_bf2(__ldg(&aggh_in[t0 * 32 + l]));
        float2 a1 = unpack_bf2(__ldg(&aggh_in[t1 * 32 + l]));
        float2 rv0 = rels[r0 * 32 + l];
        float2 rv1 = rels[r1 * 32 + l];
        acc0  = fmaf(w0 * rv0.x, a0.x, acc0);
        acc1  = fmaf(w0 * rv0.y, a0.y, acc1);
        acc0b = fmaf(w1 * rv1.x, a1.x, acc0b);
        acc1b = fmaf(w1 * rv1.y, a1.y, acc1b);
    }
    if (k < s1) {
        unsigned pk = __ldg(&g_csrt[k]);
        float w0 = __ldg(&g_attc[k]) * rinv;
        int t = pk & 0x1FFFF, r = pk >> 17;
        float2 a = unpack_bf2(__ldg(&aggh_in[t * 32 + l]));
        float2 rv = rels[r * 32 + l];
        acc0 = fmaf(w0 * rv.x, a.x, acc0);
        acc1 = fmaf(w0 * rv.y, a.y, acc1);
    }
    acc0 += acc0b; acc1 += acc1b;

    int deg = s1 - s0;
    float sc = 1.0f / (float)((deg > 1) ? deg : 1);
    acc0 *= sc; acc1 *= sc;

    float n2 = acc0 * acc0 + acc1 * acc1;
    #pragma unroll
    for (int o = 16; o; o >>= 1) n2 += __shfl_xor_sync(0xffffffffu, n2, o);
    float nrm = sqrtf(n2);
    float inv = 1.0f / fmaxf(nrm, 1e-12f);
    float v0 = acc0 * inv, v1 = acc1 * inv;

    aggh_out[w * 32 + l] = pack_bf2(v0, v1);   // bf16 row for next hop
    size_t o0 = (size_t)w * D + 2 * l, o1 = o0 + 1;
    float e0 = ent[o0], e1 = ent[o1];
    if (first) { out[o0] = v0 + e0;  out[o1] = v1 + e1; }
    else       { out[o0] += v0 + e0; out[o1] += v1 + e1; }
}

// ---------------- launcher ----------------
extern "C" void kernel_launch(void* const* d_in, const int* in_sizes, int n_in,
                              void* d_out, int out_size) {
    const float* ent      = (const float*)d_in[0];
    const float* edge_emb = (const float*)d_in[1];
    const float* qw       = (const float*)d_in[2];
    const float* kw       = (const float*)d_in[3];
    const int*   ei       = (const int*)d_in[4];
    const int*   et       = (const int*)d_in[5];
    const int* head = ei;
    const int* tail = ei + NEDGE;
    float* out = (float*)d_out;

    unsigned *aggH = nullptr, *aggH2 = nullptr;
    cudaGetSymbolAddress((void**)&aggH, g_aggH);
    cudaGetSymbolAddress((void**)&aggH2, g_aggH2);

    const int TB = 256;
    const int EB = (NEDGE + TB - 1) / TB;
    const int AGG_B = (NE + 7) / 8;

    k_prep <<<1024, TB>>>(ent, edge_emb, kw, qw);        // 0
    k_ehist<<<EB, TB>>>(et, head);                       // 1
    k_qmm  <<<NBLK_Q, 256>>>(aggH);                      // 2
    k_attmm<<<NBLK_ATT, 256>>>(aggH, head, tail);        // 3  <- ncu slot
    k_scan1<<<NB, SCAN_B>>>();                           // 4
    k_scan2<<<1, 128>>>();                               // 5
    k_scan3<<<(NE + TB - 1) / TB, TB>>>();               // 6
    k_fill <<<EB, TB>>>(head, tail, et);                 // 7
    k_agg  <<<AGG_B, 256>>>(aggH, aggH2, ent, out, edge_emb, 1);   // 8

    k_qmm  <<<NBLK_Q, 256>>>(aggH2);                     // 9
    k_attmm<<<NBLK_ATT, 256>>>(aggH2, head, tail);       // 10
    k_agg  <<<AGG_B, 256>>>(aggH2, aggH, ent, out, edge_emb, 0);   // 11
}

// round 17
// speedup vs baseline: 1.2144x; 1.2144x over previous
#include <cuda_runtime.h>
#include <cuda_bf16.h>
#include <math.h>

#define NE 100000
#define D  64
#define NEDGE 1000000
#define NR 32
#define SCAN_B 1024
#define NB ((NE + SCAN_B - 1) / SCAN_B)   // 98
#define RBIN 32768                        // slots per relation bin (mult of 128)
#define PADE (NR * RBIN)                  // 1048576
#define NBLK_ATT (PADE / 128)             // 8192
#define NBLK_Q   ((NE + 127) / 128)       // 782

// ------------- device scratch ----------------------------------------------
__device__ __align__(256) unsigned g_aggH[NE * 32];     // bf16x2 agg rows (current)
__device__ __align__(256) unsigned g_aggH2[NE * 32];    // bf16x2 agg rows (next)
__device__ __align__(256) unsigned g_Qu[NE * 32];       // bf16x2 Q rows
__device__ __align__(256) float    g_att[NEDGE];
__device__ __align__(256) float    g_attc[NEDGE];       // exp(att) in CSR order
__device__ __align__(256) unsigned g_KRt[NR * D * 32];  // bf16x2, [r][n][k2]
__device__ __align__(256) unsigned g_QWt[D * 32];       // bf16x2, [n][k2]
__device__ __align__(256) int      g_deg[NE];
__device__ __align__(256) int      g_fill[NE];
__device__ __align__(256) int      g_rowptr[NE + 1];
__device__ __align__(256) int      g_csr[NEDGE];
__device__ __align__(256) unsigned g_csrt[NEDGE];       // tail | etype<<17 in CSR order
__device__ __align__(256) int      g_part[NB + 8];
__device__ __align__(256) int      g_rfill[NR];
__device__ __align__(256) int      g_eord[PADE];

// ---------------- helpers ----------------
__device__ __forceinline__ unsigned pack_bf2(float lo, float hi) {
    __nv_bfloat162 b = __float22bfloat162_rn(make_float2(lo, hi));  // .x = lo
    return *reinterpret_cast<unsigned*>(&b);
}
__device__ __forceinline__ float2 unpack_bf2(unsigned u) {
    __nv_bfloat162 b = *reinterpret_cast<__nv_bfloat162*>(&u);
    return __bfloat1622float2(b);
}

__device__ __forceinline__ void mma_bf16(float& c0, float& c1, float& c2, float& c3,
                                         unsigned a0, unsigned a1, unsigned a2, unsigned a3,
                                         unsigned b0, unsigned b1) {
    asm("mma.sync.aligned.m16n8k16.row.col.f32.bf16.bf16.f32 "
        "{%0,%1,%2,%3},{%4,%5,%6,%7},{%8,%9},{%0,%1,%2,%3};"
        : "+f"(c0), "+f"(c1), "+f"(c2), "+f"(c3)
        : "r"(a0), "r"(a1), "r"(a2), "r"(a3), "r"(b0), "r"(b1));
}

// cp.async 4B helpers
__device__ __forceinline__ void cpa4(void* sptr, const void* gptr) {
    unsigned sa = (unsigned)__cvta_generic_to_shared(sptr);
    asm volatile("cp.async.ca.shared.global [%0], [%1], 4;" :: "r"(sa), "l"(gptr));
}
__device__ __forceinline__ void cpa_commit() {
    asm volatile("cp.async.commit_group;");
}
template <int N>
__device__ __forceinline__ void cpa_wait() {
    asm volatile("cp.async.wait_group %0;" :: "n"(N));
}

// Taylor-7 tanh: |s| small; clamp at +-1.
__device__ __forceinline__ float tanhp(float x) {
    x = fminf(1.0f, fmaxf(-1.0f, x));
    float u = x * x;
    float p = fmaf(u, -17.0f / 315.0f, 2.0f / 15.0f);
    p = fmaf(u, p, -1.0f / 3.0f);
    p = fmaf(u, p, 1.0f);
    return x * p;
}

#define XU_STRIDE 36
#define QS_STRIDE 33

// ---------------- prep: packed bf16 weights + ent->bf16 + init -------------
__global__ void k_prep(const float* __restrict__ ent, const float* __restrict__ edge_emb,
                       const float* __restrict__ kw, const float* __restrict__ qw) {
    int tid = blockIdx.x * blockDim.x + threadIdx.x;
    int st = gridDim.x * blockDim.x;
    for (int i = tid; i < NR * D * 32; i += st) {
        int r = i >> 11, rm = i & 2047;
        int n = rm >> 5, k2 = rm & 31;
        float rlo = edge_emb[r * 64 + 2 * k2], rhi = edge_emb[r * 64 + 2 * k2 + 1];
        float klo = kw[(2 * k2) * 64 + n],     khi = kw[(2 * k2 + 1) * 64 + n];
        g_KRt[i] = pack_bf2(rlo * klo, rhi * khi);
    }
    for (int i = tid; i < D * 32; i += st) {
        int n = i >> 5, k2 = i & 31;
        g_QWt[i] = pack_bf2(qw[(2 * k2) * 64 + n], qw[(2 * k2 + 1) * 64 + n]);
    }
    for (int i = tid; i < NE * 32; i += st) {
        int row = i >> 5, k2 = i & 31;
        g_aggH[i] = pack_bf2(ent[row * 64 + 2 * k2], ent[row * 64 + 2 * k2 + 1]);
    }
    for (int i = tid; i < NE; i += st) { g_deg[i] = 0; g_fill[i] = 0; }
    if (tid < NR) g_rfill[tid] = 0;
}

// ------ relation binning (block-aggregated atomics) + degree histogram -----
__global__ void k_ehist(const int* __restrict__ etype, const int* __restrict__ head) {
    __shared__ int hist[NR];
    __shared__ int rbase[NR];
    int tid = threadIdx.x;
    int e = blockIdx.x * blockDim.x + tid;
    if (tid < NR) hist[tid] = 0;
    __syncthreads();
    int r = 0, off = 0;
    bool valid = (e < NEDGE);
    if (valid) {
        r = etype[e];
        off = atomicAdd(&hist[r], 1);                 // smem atomic
        atomicAdd(&g_deg[head[e]], 1);                // 100K addrs: low contention
    }
    __syncthreads();
    if (tid < NR && hist[tid] > 0)
        rbase[tid] = atomicAdd(&g_rfill[tid], hist[tid]);  // 32 atomics/block
    __syncthreads();
    if (valid) g_eord[(r << 15) + rbase[r] + off] = e;
}

// ---------------- CSR build ----------------
__global__ void k_scan1() {
    __shared__ int sh[SCAN_B];
    int b = blockIdx.x, t = threadIdx.x;
    int i = b * SCAN_B + t;
    int v = (i < NE) ? g_deg[i] : 0;
    sh[t] = v;
    __syncthreads();
    #pragma unroll
    for (int off = 1; off < SCAN_B; off <<= 1) {
        int x = (t >= off) ? sh[t - off] : 0;
        __syncthreads();
        sh[t] += x;
        __syncthreads();
    }
    if (i < NE) g_rowptr[i] = sh[t] - v;
    if (t == SCAN_B - 1) g_part[b] = sh[t];
}

__global__ void k_scan2() {       // parallel exclusive scan over NB block sums
    __shared__ int sh[128];
    int t = threadIdx.x;
    int v = (t < NB) ? g_part[t] : 0;
    sh[t] = v;
    __syncthreads();
    #pragma unroll
    for (int off = 1; off < 128; off <<= 1) {
        int x = (t >= off) ? sh[t - off] : 0;
        __syncthreads();
        sh[t] += x;
        __syncthreads();
    }
    if (t < NB) g_part[t] = sh[t] - v;
}

__global__ void k_scan3() {
    int i = blockIdx.x * blockDim.x + threadIdx.x;
    if (i < NE) g_rowptr[i] += g_part[i >> 10];
    if (i == 0) g_rowptr[NE] = NEDGE;
}

__global__ void k_fill(const int* __restrict__ head, const int* __restrict__ tail,
                       const int* __restrict__ etype) {
    int e = blockIdx.x * blockDim.x + threadIdx.x;
    if (e < NEDGE) {
        int h = head[e];
        int p = g_rowptr[h] + atomicAdd(&g_fill[h], 1);
        g_csr[p] = e;
        g_csrt[p] = (unsigned)tail[e] | ((unsigned)etype[e] << 17);
    }
}

// ----- MMA core: per-warp M=16 (rows w*16..w*16+15), full N=64, K=64 -------
__device__ __forceinline__ void mma_core16(const unsigned* Xu, const unsigned* Bu,
                                           float acc[8][4], int w, int lane) {
    int grp = lane >> 2, c4 = lane & 3;
    #pragma unroll
    for (int s = 0; s < 4; s++) {
        int ar = w * 16 + grp;
        unsigned a0 = Xu[ar * XU_STRIDE + s * 8 + c4];
        unsigned a1 = Xu[(ar + 8) * XU_STRIDE + s * 8 + c4];
        unsigned a2 = Xu[ar * XU_STRIDE + s * 8 + c4 + 4];
        unsigned a3 = Xu[(ar + 8) * XU_STRIDE + s * 8 + c4 + 4];
        #pragma unroll
        for (int n = 0; n < 8; n++) {
            unsigned b0 = Bu[(n * 8 + grp) * XU_STRIDE + s * 8 + c4];
            unsigned b1 = Bu[(n * 8 + grp) * XU_STRIDE + s * 8 + c4 + 4];
            mma_bf16(acc[n][0], acc[n][1], acc[n][2], acc[n][3],
                     a0, a1, a2, a3, b0, b1);
        }
    }
}

// ---------------- Q = aggh @ q_w via bf16 mma (256 thr, 128 rows) ----------
__global__ void __launch_bounds__(256, 4) k_qmm(const unsigned* __restrict__ aggh) {
    __shared__ unsigned Xu[128 * XU_STRIDE];
    __shared__ unsigned Bu[64 * XU_STRIDE];
    int tid = threadIdx.x;
    int w = tid >> 5, lane = tid & 31;
    int base = blockIdx.x * 128;

    #pragma unroll
    for (int rr = 0; rr < 16; rr++) {
        int row = w * 16 + rr;
        int g = base + row;
        if (g < NE) cpa4(&Xu[row * XU_STRIDE + lane], &aggh[g * 32 + lane]);
        else        Xu[row * XU_STRIDE + lane] = 0u;
    }
    #pragma unroll
    for (int i = tid; i < D * 32; i += 256) {
        int n = i >> 5, k2 = i & 31;
        cpa4(&Bu[n * XU_STRIDE + k2], &g_QWt[i]);
    }
    cpa_commit();
    cpa_wait<0>();
    __syncthreads();

    float acc[8][4];
    #pragma unroll
    for (int n = 0; n < 8; n++)
        #pragma unroll
        for (int q = 0; q < 4; q++) acc[n][q] = 0.0f;

    mma_core16(Xu, Bu, acc, w, lane);

    int grp = lane >> 2, c4 = lane & 3;
    int r0 = base + w * 16 + grp, r1 = r0 + 8;
    #pragma unroll
    for (int n = 0; n < 8; n++) {
        if (r0 < NE) g_Qu[r0 * 32 + n * 4 + c4] = pack_bf2(acc[n][0], acc[n][1]);
        if (r1 < NE) g_Qu[r1 * 32 + n * 4 + c4] = pack_bf2(acc[n][2], acc[n][3]);
    }
}

// ------- att[e] = <Q[head], tanh(aggh[tail] @ KR[r])> via bf16 mma ---------
__global__ void __launch_bounds__(256, 4) k_attmm(const unsigned* __restrict__ aggh,
                                                  const int* __restrict__ head,
                                                  const int* __restrict__ tail) {
    int base = blockIdx.x * 128;
    int rel = blockIdx.x >> 8;          // 256 blocks per static relation bin
    int cnt = g_rfill[rel] - ((blockIdx.x & 255) << 7);   // valid edges this block
    if (cnt <= 0) return;

    __shared__ unsigned Xu[128 * XU_STRIDE];
    __shared__ unsigned Bu[64 * XU_STRIDE];
    __shared__ unsigned Qs[128 * QS_STRIDE];
    __shared__ int es[128];
    __shared__ int tls[128];
    __shared__ int hds[128];
    int tid = threadIdx.x;
    int w = tid >> 5, lane = tid & 31;

    if (tid < 128) {
        int e = (tid < cnt) ? g_eord[base + tid] : -1;
        es[tid] = e;
        tls[tid] = (e >= 0) ? __ldg(&tail[e]) : 0;
        hds[tid] = (e >= 0) ? __ldg(&head[e]) : 0;
    }
    __syncthreads();

    // group A: X gather + B tile
    #pragma unroll
    for (int rr = 0; rr < 16; rr++) {
        int row = w * 16 + rr;
        cpa4(&Xu[row * XU_STRIDE + lane], &aggh[tls[row] * 32 + lane]);
    }
    #pragma unroll
    for (int i = tid; i < D * 32; i += 256) {
        int n = i >> 5, k2 = i & 31;
        cpa4(&Bu[n * XU_STRIDE + k2], &g_KRt[rel * D * 32 + i]);
    }
    cpa_commit();
    // group B: Q rows prefetch (consumed after MMA, warp-local rows)
    #pragma unroll
    for (int rr = 0; rr < 16; rr++) {
        int row = w * 16 + rr;
        cpa4(&Qs[row * QS_STRIDE + lane], &g_Qu[hds[row] * 32 + lane]);
    }
    cpa_commit();

    cpa_wait<1>();        // X + B landed; Q still in flight
    __syncthreads();

    float acc[8][4];
    #pragma unroll
    for (int n = 0; n < 8; n++)
        #pragma unroll
        for (int q = 0; q < 4; q++) acc[n][q] = 0.0f;

    mma_core16(Xu, Bu, acc, w, lane);

    cpa_wait<0>();        // Q rows landed (own warp's rows)
    __syncwarp();

    // epilogue: att = sum_j Q[head][j] * tanh(S[row][j]) from smem Qs
    int grp = lane >> 2, c4 = lane & 3;
    int rl0 = w * 16 + grp, rl1 = rl0 + 8;
    int e0 = es[rl0], e1 = es[rl1];
    float s0 = 0.0f, s1 = 0.0f;
    #pragma unroll
    for (int n = 0; n < 8; n++) {
        float2 q0 = unpack_bf2(Qs[rl0 * QS_STRIDE + n * 4 + c4]);
        float2 q1 = unpack_bf2(Qs[rl1 * QS_STRIDE + n * 4 + c4]);
        s0 = fmaf(q0.x, tanhp(acc[n][0]), fmaf(q0.y, tanhp(acc[n][1]), s0));
        s1 = fmaf(q1.x, tanhp(acc[n][2]), fmaf(q1.y, tanhp(acc[n][3]), s1));
    }
    s0 += __shfl_xor_sync(0xffffffffu, s0, 1);
    s0 += __shfl_xor_sync(0xffffffffu, s0, 2);
    s1 += __shfl_xor_sync(0xffffffffu, s1, 1);
    s1 += __shfl_xor_sync(0xffffffffu, s1, 2);
    if (c4 == 0) {
        if (e0 >= 0) g_att[e0] = s0;
        if (e1 >= 0) g_att[e1] = s1;
    }
}

// ------- softmax (no-max) + weighted mean (bf16 gather) + l2norm + residual
__global__ void __launch_bounds__(256) k_agg(const unsigned* __restrict__ aggh_in,
                                             unsigned* __restrict__ aggh_out,
                                             const float* __restrict__ ent,
                                             float* __restrict__ out,
                                             const float* __restrict__ edge_emb,
                                             int first) {
    __shared__ float2 rels[NR * 32];   // 8KB relation table, pair layout
    for (int i = threadIdx.x; i < NR * 32; i += 256)
        rels[i] = make_float2(edge_emb[2 * i], edge_emb[2 * i + 1]);
    __syncthreads();

    int w = (blockIdx.x * blockDim.x + threadIdx.x) >> 5;
    int l = threadIdx.x & 31;
    if (w >= NE) return;
    int s0 = g_rowptr[w], s1 = g_rowptr[w + 1];

    // pass 1: exp into CSR-ordered attc (random att read, sequential write)
    float den = 0.0f;
    for (int k = s0 + l; k < s1; k += 32) {
        float a = __expf(g_att[g_csr[k]]);
        g_attc[k] = a;
        den += a;
    }
    #pragma unroll
    for (int o = 16; o; o >>= 1) den += __shfl_xor_sync(0xffffffffu, den, o);
    float rinv = (den > 0.0f) ? (1.0f / den) : 0.0f;

    // pass 2: all-sequential metadata; only the aggh gather is random.
    float acc0 = 0.0f, acc1 = 0.0f;
    if (s0 < s1) {
        unsigned pk = __ldg(&g_csrt[s0]);
        for (int k = s0; k < s1; k++) {
            unsigned pkn = (k + 1 < s1) ? __ldg(&g_csrt[k + 1]) : 0u;
            int t = pk & 0x1FFFF, r = pk >> 17;
            float2 a = unpack_bf2(__ldg(&aggh_in[t * 32 + l]));
            float wgt = __ldg(&g_attc[k]) * rinv;
            float2 rv = rels[r * 32 + l];
            acc0 = fmaf(wgt * rv.x, a.x, acc0);
            acc1 = fmaf(wgt * rv.y, a.y, acc1);
            pk = pkn;
        }
    }

    int deg = s1 - s0;
    float sc = 1.0f / (float)((deg > 1) ? deg : 1);
    acc0 *= sc; acc1 *= sc;

    float n2 = acc0 * acc0 + acc1 * acc1;
    #pragma unroll
    for (int o = 16; o; o >>= 1) n2 += __shfl_xor_sync(0xffffffffu, n2, o);
    float nrm = sqrtf(n2);
    float inv = 1.0f / fmaxf(nrm, 1e-12f);
    float v0 = acc0 * inv, v1 = acc1 * inv;

    aggh_out[w * 32 + l] = pack_bf2(v0, v1);   // bf16 row for next hop
    size_t o0 = (size_t)w * D + 2 * l, o1 = o0 + 1;
    float e0 = ent[o0], e1 = ent[o1];
    if (first) { out[o0] = v0 + e0;  out[o1] = v1 + e1; }
    else       { out[o0] += v0 + e0; out[o1] += v1 + e1; }
}

// ---------------- launcher ----------------
extern "C" void kernel_launch(void* const* d_in, const int* in_sizes, int n_in,
                              void* d_out, int out_size) {
    const float* ent      = (const float*)d_in[0];
    const float* edge_emb = (const float*)d_in[1];
    const float* qw       = (const float*)d_in[2];
    const float* kw       = (const float*)d_in[3];
    const int*   ei       = (const int*)d_in[4];
    const int*   et       = (const int*)d_in[5];
    const int* head = ei;
    const int* tail = ei + NEDGE;
    float* out = (float*)d_out;

    unsigned *aggH = nullptr, *aggH2 = nullptr;
    cudaGetSymbolAddress((void**)&aggH, g_aggH);
    cudaGetSymbolAddress((void**)&aggH2, g_aggH2);

    const int TB = 256;
    const int EB = (NEDGE + TB - 1) / TB;
    const int AGG_B = (NE + 7) / 8;

    k_prep <<<1024, TB>>>(ent, edge_emb, kw, qw);        // 0
    k_ehist<<<EB, TB>>>(et, head);                       // 1
    k_qmm  <<<NBLK_Q, 256>>>(aggH);                      // 2
    k_attmm<<<NBLK_ATT, 256>>>(aggH, head, tail);        // 3  <- ncu slot
    k_scan1<<<NB, SCAN_B>>>();                           // 4
    k_scan2<<<1, 128>>>();                               // 5
    k_scan3<<<(NE + TB - 1) / TB, TB>>>();               // 6
    k_fill <<<EB, TB>>>(head, tail, et);                 // 7
    k_agg  <<<AGG_B, 256>>>(aggH, aggH2, ent, out, edge_emb, 1);   // 8

    k_qmm  <<<NBLK_Q, 256>>>(aggH2);                     // 9
    k_attmm<<<NBLK_ATT, 256>>>(aggH2, head, tail);       // 10
    k_agg  <<<AGG_B, 256>>>(aggH2, aggH, ent, out, edge_emb, 0);   // 11
}